// round 1
// baseline (speedup 1.0000x reference)
#include <cuda_runtime.h>
#include <math.h>

#define V_A   256
#define V_HP  256
#define H_A   2048
#define H_HP  4096
#define DEPTH 12

#define NBLK 148
#define NTHR 512
#define NWARP_BLK (NTHR / 32)
#define NWARPS (NBLK * NWARP_BLK)   // 2368

// ---------------- persistent device state ----------------
__device__ float g_a[V_A];
__device__ float g_ahp[V_HP];
__device__ float g_ha[H_A];
__device__ float g_ca[2][H_A];          // double buffered (read+write same stage)
__device__ float g_hhp[H_HP];
__device__ float g_chp[H_HP];
__device__ float g_gates_a[4 * H_A];
__device__ float g_gates_hp[4 * H_HP];
__device__ float g_hsum[H_A];
__device__ float g_lpa[2][V_A];          // logits_a partials (K split in 2)
__device__ float g_lphp[4][V_HP];        // logits_hp partials (K split in 4)
__device__ unsigned int g_bar_count = 0;
__device__ unsigned int g_bar_gen = 0;

// ---------------- grid barrier (all 148 blocks resident) ----------------
__device__ __forceinline__ void grid_sync() {
    __syncthreads();
    if (threadIdx.x == 0) {
        __threadfence();
        volatile unsigned int* vgen = &g_bar_gen;
        unsigned int gen = *vgen;
        unsigned int ticket = atomicAdd(&g_bar_count, 1);
        if (ticket == gridDim.x - 1) {
            g_bar_count = 0;
            __threadfence();
            *vgen = gen + 1;
        } else {
            while (*vgen == gen) { }
        }
    }
    __syncthreads();
}

__device__ __forceinline__ float sigm(float x) { return 1.0f / (1.0f + expf(-x)); }

__device__ __forceinline__ float wred(float v) {
    #pragma unroll
    for (int o = 16; o; o >>= 1) v += __shfl_xor_sync(0xffffffffu, v, o);
    return v;
}

// lane-partial dot of a W row (global) with x (shared). K4 = K/4, multiple of 64.
__device__ __forceinline__ float wdotp(const float* __restrict__ W,
                                       const float* __restrict__ xs,
                                       int K4, int lane) {
    const float4* __restrict__ W4 = (const float4*)W;
    const float4* __restrict__ x4 = (const float4*)xs;
    float a0 = 0.f, a1 = 0.f;
    #pragma unroll 2
    for (int i = lane; i < K4; i += 64) {
        float4 w = W4[i];      float4 x = x4[i];
        a0 = fmaf(w.x, x.x, fmaf(w.y, x.y, fmaf(w.z, x.z, fmaf(w.w, x.w, a0))));
        float4 w2 = W4[i + 32]; float4 x2 = x4[i + 32];
        a1 = fmaf(w2.x, x2.x, fmaf(w2.y, x2.y, fmaf(w2.z, x2.z, fmaf(w2.w, x2.w, a1))));
    }
    return a0 + a1;
}

// warp-collective softmax over 256 logits assembled from nch K-split partials + bias.
// res8[k] is the probability for index (lane + 32k). Fixed reduce order -> deterministic.
__device__ __forceinline__ void warp_softmax_256(const float* parts, int nch,
                                                 const float* __restrict__ bias,
                                                 int lane, float* res8) {
    float v[8];
    float mx = -1e30f;
    #pragma unroll
    for (int k = 0; k < 8; ++k) {
        int j = lane + 32 * k;
        float s = bias[j];
        for (int c = 0; c < nch; ++c) s += __ldcg(&parts[c * 256 + j]);
        v[k] = s;
        mx = fmaxf(mx, s);
    }
    #pragma unroll
    for (int o = 16; o; o >>= 1) mx = fmaxf(mx, __shfl_xor_sync(0xffffffffu, mx, o));
    float sum = 0.f;
    #pragma unroll
    for (int k = 0; k < 8; ++k) { v[k] = expf(v[k] - mx); sum += v[k]; }
    sum = wred(sum);
    #pragma unroll
    for (int k = 0; k < 8; ++k) res8[k] = v[k] / sum;
}

__global__ void __launch_bounds__(NTHR, 1) archdec_kernel(
    const float* __restrict__ xa,     const float* __restrict__ xhp,
    const float* __restrict__ W_ih_a, const float* __restrict__ W_hh_a,
    const float* __restrict__ b_ih_a, const float* __restrict__ b_hh_a,
    const float* __restrict__ W_out_a, const float* __restrict__ b_out_a,
    const float* __restrict__ W_sum,  const float* __restrict__ b_sum,
    const float* __restrict__ W_ih_hp, const float* __restrict__ W_hh_hp,
    const float* __restrict__ b_ih_hp, const float* __restrict__ b_hh_hp,
    const float* __restrict__ W_out_hp, const float* __restrict__ b_out_hp,
    float* __restrict__ out)
{
    __shared__ float sm[V_A + H_A + H_HP + H_HP];   // 10496 floats = 41 KB
    const int tid  = threadIdx.x;
    const int lane = tid & 31;
    const int wid  = tid >> 5;
    const int gw   = blockIdx.x * NWARP_BLK + wid;

    // -------- init state (every launch) --------
    {
        int j = blockIdx.x * NTHR + tid;
        if (j < H_HP) {
            if (j < V_A) { __stcg(&g_a[j], 1.0f / V_A); __stcg(&g_ahp[j], 1.0f / V_HP); }
            if (j < H_A) { __stcg(&g_ha[j], xa[j]); __stcg(&g_ca[0][j], 0.f); }
            __stcg(&g_hhp[j], xhp[j]);
            __stcg(&g_chp[j], 0.f);
        }
    }
    grid_sync();

    for (int t = 0; t < DEPTH; ++t) {
        // ================= PHASE 1: big GEMVs on prev-step state =================
        float* sa   = sm;                 // 256
        float* sha  = sm + V_A;           // 2048
        float* shhp = sha + H_A;          // 4096
        float* schp = shhp + H_HP;        // 4096
        for (int j = tid; j < V_A;  j += NTHR) sa[j]  = __ldcg(&g_a[j]);
        for (int j = tid; j < H_A;  j += NTHR) sha[j] = __ldcg(&g_ha[j]);
        for (int j = tid; j < H_HP; j += NTHR) { shhp[j] = __ldcg(&g_hhp[j]); schp[j] = __ldcg(&g_chp[j]); }
        __syncthreads();

        // block 0 / warp 0: finish previous step's a_hp = softmax(logits_hp(t-1))
        if (t > 0 && blockIdx.x == 0 && wid == 0) {
            float r8[8];
            warp_softmax_256(&g_lphp[0][0], 4, b_out_hp, lane, r8);
            #pragma unroll
            for (int k = 0; k < 8; ++k) {
                int j = lane + 32 * k;
                __stcg(&g_ahp[j], r8[k]);
                out[DEPTH * V_A + (t - 1) * V_HP + j] = r8[k];
            }
        }

        // gates_a = W_ih_a @ a + W_hh_a @ h_a + b    (8192 rows)
        for (int r = gw; r < 4 * H_A; r += NWARPS) {
            float p = wdotp(W_ih_a + (size_t)r * V_A, sa,  V_A / 4, lane)
                    + wdotp(W_hh_a + (size_t)r * H_A, sha, H_A / 4, lane);
            p = wred(p);
            if (lane == 0) __stcg(&g_gates_a[r], p + b_ih_a[r] + b_hh_a[r]);
        }
        // h_sum = relu(W_sum @ h_hp + b)             (2048 rows)
        for (int r = gw; r < H_A; r += NWARPS) {
            float p = wred(wdotp(W_sum + (size_t)r * H_HP, shhp, H_HP / 4, lane));
            if (lane == 0) __stcg(&g_hsum[r], fmaxf(p + b_sum[r], 0.f));
        }
        // gates_hp = W_hh_hp @ c_hp + b_ih + b_hh    (16384 rows, 268 MB)
        for (int r = gw; r < 4 * H_HP; r += NWARPS) {
            float p = wred(wdotp(W_hh_hp + (size_t)r * H_HP, schp, H_HP / 4, lane));
            if (lane == 0) __stcg(&g_gates_hp[r], p + b_ih_hp[r] + b_hh_hp[r]);
        }
        grid_sync();

        // ================= S1: arch cell + logits_a partials =================
        if (blockIdx.x < 32) {
            float* sh2 = sm;                 // h_a(t), 2048
            const int cb = t & 1;
            for (int j = tid; j < H_A; j += NTHR) {
                float ig = __ldcg(&g_gates_a[j]);
                float fg = __ldcg(&g_gates_a[H_A + j]);
                float gg = __ldcg(&g_gates_a[2 * H_A + j]);
                float og = __ldcg(&g_gates_a[3 * H_A + j]);
                float cn = sigm(fg) * __ldcg(&g_ca[cb][j]) + sigm(ig) * tanhf(gg);
                float hn = sigm(og) * tanhf(cn);
                sh2[j] = hn;
                if (blockIdx.x == 0) { __stcg(&g_ha[j], hn); __stcg(&g_ca[1 - cb][j], cn); }
            }
            __syncthreads();
            // logits_a partials: 512 warps, row = gw&255, K-chunk = gw>>8 (1024 each)
            if (gw < 512) {
                int r  = gw & (V_A - 1);
                int ch = gw >> 8;
                float p = wred(wdotp(W_out_a + (size_t)r * H_A + ch * 1024, sh2 + ch * 1024, 256, lane));
                if (lane == 0) __stcg(&g_lpa[ch][r], p);
            }
        }
        grid_sync();

        // ================= S2: softmax(a) + W_ih_hp accumulate =================
        {
            float* sinp = sm;  // [a(t) | a_hp(t-1)] = 512
            if (wid == 0) {
                float r8[8];
                warp_softmax_256(&g_lpa[0][0], 2, b_out_a, lane, r8);
                #pragma unroll
                for (int k = 0; k < 8; ++k) {
                    int j = lane + 32 * k;
                    sinp[j] = r8[k];
                    if (blockIdx.x == 0) { __stcg(&g_a[j], r8[k]); out[t * V_A + j] = r8[k]; }
                }
            } else if (wid == 1) {
                for (int j = lane; j < V_HP; j += 32) sinp[V_A + j] = __ldcg(&g_ahp[j]);
            }
            __syncthreads();
            for (int r = gw; r < 4 * H_HP; r += NWARPS) {
                float p = wred(wdotp(W_ih_hp + (size_t)r * (V_A + V_HP), sinp, (V_A + V_HP) / 4, lane));
                if (lane == 0) __stcg(&g_gates_hp[r], __ldcg(&g_gates_hp[r]) + p);
            }
        }
        grid_sync();

        // ================= S3: hp cell + logits_hp partials =================
        // NOTE swapped hx in the reference: h-input was c_hp(t-1) (already consumed in the
        // GEMV), and the CELL state is prev_h_hp = concat(h_a(t), h_sum).
        if (blockIdx.x < 64) {
            float* sh2 = sm;                 // h_hp(t), 4096
            for (int j = tid; j < H_HP; j += NTHR) {
                float ig = __ldcg(&g_gates_hp[j]);
                float fg = __ldcg(&g_gates_hp[H_HP + j]);
                float gg = __ldcg(&g_gates_hp[2 * H_HP + j]);
                float og = __ldcg(&g_gates_hp[3 * H_HP + j]);
                float pc = (j < H_A) ? __ldcg(&g_ha[j]) : __ldcg(&g_hsum[j - H_A]);
                float cn = sigm(fg) * pc + sigm(ig) * tanhf(gg);
                float hn = sigm(og) * tanhf(cn);
                sh2[j] = hn;
                if (blockIdx.x == 0) { __stcg(&g_hhp[j], hn); __stcg(&g_chp[j], cn); }
            }
            __syncthreads();
            // logits_hp partials: 1024 warps, row = gw&255, K-chunk = gw>>8 (1024 each)
            if (gw < 1024) {
                int r  = gw & (V_HP - 1);
                int ch = gw >> 8;
                float p = wred(wdotp(W_out_hp + (size_t)r * H_HP + ch * 1024, sh2 + ch * 1024, 256, lane));
                if (lane == 0) __stcg(&g_lphp[ch][r], p);
            }
        }
        grid_sync();
    }

    // ================= epilogue: final a_hp row =================
    if (blockIdx.x == 0 && wid == 0) {
        float r8[8];
        warp_softmax_256(&g_lphp[0][0], 4, b_out_hp, lane, r8);
        #pragma unroll
        for (int k = 0; k < 8; ++k) {
            int j = lane + 32 * k;
            out[DEPTH * V_A + (DEPTH - 1) * V_HP + j] = r8[k];
        }
    }
}

extern "C" void kernel_launch(void* const* d_in, const int* in_sizes, int n_in,
                              void* d_out, int out_size) {
    (void)in_sizes; (void)n_in; (void)out_size;
    archdec_kernel<<<NBLK, NTHR>>>(
        (const float*)d_in[0],  (const float*)d_in[1],
        (const float*)d_in[2],  (const float*)d_in[3],
        (const float*)d_in[4],  (const float*)d_in[5],
        (const float*)d_in[6],  (const float*)d_in[7],
        (const float*)d_in[8],  (const float*)d_in[9],
        (const float*)d_in[10], (const float*)d_in[11],
        (const float*)d_in[12], (const float*)d_in[13],
        (const float*)d_in[14], (const float*)d_in[15],
        (float*)d_out);
}

// round 3
// speedup vs baseline: 1.2824x; 1.2824x over previous
#include <cuda_runtime.h>
#include <math.h>

#define V_A   256
#define V_HP  256
#define H_A   2048
#define H_HP  4096
#define DEPTH 12

#define NBLK 148
#define NTHR 1024
#define NWARP_BLK (NTHR / 32)
#define NWARPS (NBLK * NWARP_BLK)   // 4736

// ---------------- persistent device state ----------------
__device__ float g_a[V_A];
__device__ float g_ahp[V_HP];
__device__ float g_ha[H_A];
__device__ float g_ca[2][H_A];          // double buffered (read+write same stage)
__device__ float g_hhp[H_HP];
__device__ float g_chp[H_HP];
__device__ float g_gates_a[4 * H_A];
__device__ float g_gates_hp[4 * H_HP];
__device__ float g_hsum[H_A];
__device__ float g_lpa[2][V_A];          // logits_a partials (K split in 2)
__device__ float g_lphp[4][V_HP];        // logits_hp partials (K split in 4)
__device__ unsigned int g_bar_count = 0;
__device__ unsigned int g_bar_gen = 0;

// ---------------- grid barrier (all 148 blocks resident) ----------------
__device__ __forceinline__ void grid_sync() {
    __syncthreads();
    if (threadIdx.x == 0) {
        __threadfence();
        volatile unsigned int* vgen = &g_bar_gen;
        unsigned int gen = *vgen;
        unsigned int ticket = atomicAdd(&g_bar_count, 1);
        if (ticket == gridDim.x - 1) {
            g_bar_count = 0;
            __threadfence();
            *vgen = gen + 1;
        } else {
            while (*vgen == gen) { }
        }
    }
    __syncthreads();
}

__device__ __forceinline__ float sigm(float x) { return 1.0f / (1.0f + expf(-x)); }

__device__ __forceinline__ float wred(float v) {
    #pragma unroll
    for (int o = 16; o; o >>= 1) v += __shfl_xor_sync(0xffffffffu, v, o);
    return v;
}

// lane-partial dot of a W row (global) with x (shared). K4 = K/4, multiple of 64.
__device__ __forceinline__ float wdotp(const float* __restrict__ W,
                                       const float* __restrict__ xs,
                                       int K4, int lane) {
    const float4* __restrict__ W4 = (const float4*)W;
    const float4* __restrict__ x4 = (const float4*)xs;
    float a0 = 0.f, a1 = 0.f;
    #pragma unroll 2
    for (int i = lane; i < K4; i += 64) {
        float4 w = W4[i];      float4 x = x4[i];
        a0 = fmaf(w.x, x.x, fmaf(w.y, x.y, fmaf(w.z, x.z, fmaf(w.w, x.w, a0))));
        float4 w2 = W4[i + 32]; float4 x2 = x4[i + 32];
        a1 = fmaf(w2.x, x2.x, fmaf(w2.y, x2.y, fmaf(w2.z, x2.z, fmaf(w2.w, x2.w, a1))));
    }
    return a0 + a1;
}

// warp-collective softmax over 256 logits assembled from nch K-split partials + bias.
__device__ __forceinline__ void warp_softmax_256(const float* parts, int nch,
                                                 const float* __restrict__ bias,
                                                 int lane, float* res8) {
    float v[8];
    float mx = -1e30f;
    #pragma unroll
    for (int k = 0; k < 8; ++k) {
        int j = lane + 32 * k;
        float s = bias[j];
        for (int c = 0; c < nch; ++c) s += __ldcg(&parts[c * 256 + j]);
        v[k] = s;
        mx = fmaxf(mx, s);
    }
    #pragma unroll
    for (int o = 16; o; o >>= 1) mx = fmaxf(mx, __shfl_xor_sync(0xffffffffu, mx, o));
    float sum = 0.f;
    #pragma unroll
    for (int k = 0; k < 8; ++k) { v[k] = expf(v[k] - mx); sum += v[k]; }
    sum = wred(sum);
    #pragma unroll
    for (int k = 0; k < 8; ++k) res8[k] = v[k] / sum;
}

__global__ void __launch_bounds__(NTHR, 1) archdec_kernel(
    const float* __restrict__ xa,     const float* __restrict__ xhp,
    const float* __restrict__ W_ih_a, const float* __restrict__ W_hh_a,
    const float* __restrict__ b_ih_a, const float* __restrict__ b_hh_a,
    const float* __restrict__ W_out_a, const float* __restrict__ b_out_a,
    const float* __restrict__ W_sum,  const float* __restrict__ b_sum,
    const float* __restrict__ W_ih_hp, const float* __restrict__ W_hh_hp,
    const float* __restrict__ b_ih_hp, const float* __restrict__ b_hh_hp,
    const float* __restrict__ W_out_hp, const float* __restrict__ b_out_hp,
    float* __restrict__ out)
{
    __shared__ float sm[V_A + H_A + H_HP + H_HP];   // 10496 floats = 41 KB
    const int tid  = threadIdx.x;
    const int lane = tid & 31;
    const int wid  = tid >> 5;
    const int gw   = blockIdx.x * NWARP_BLK + wid;

    // -------- init state (every launch) --------
    {
        int j = blockIdx.x * NTHR + tid;
        if (j < H_HP) {
            if (j < V_A) { __stcg(&g_a[j], 1.0f / V_A); __stcg(&g_ahp[j], 1.0f / V_HP); }
            if (j < H_A) { __stcg(&g_ha[j], xa[j]); __stcg(&g_ca[0][j], 0.f); }
            __stcg(&g_hhp[j], xhp[j]);
            __stcg(&g_chp[j], 0.f);
        }
    }
    grid_sync();

    for (int t = 0; t < DEPTH; ++t) {
        // ================= PHASE 1: big GEMVs on prev-step state =================
        float* sa   = sm;                 // 256
        float* sha  = sm + V_A;           // 2048
        float* shhp = sha + H_A;          // 4096
        float* schp = shhp + H_HP;        // 4096
        for (int j = tid; j < V_A;  j += NTHR) sa[j]  = __ldcg(&g_a[j]);
        for (int j = tid; j < H_A;  j += NTHR) sha[j] = __ldcg(&g_ha[j]);
        for (int j = tid; j < H_HP; j += NTHR) { shhp[j] = __ldcg(&g_hhp[j]); schp[j] = __ldcg(&g_chp[j]); }
        __syncthreads();

        // block 0 / warp 0: finish previous step's a_hp = softmax(logits_hp(t-1))
        if (t > 0 && blockIdx.x == 0 && wid == 0) {
            float r8[8];
            warp_softmax_256(&g_lphp[0][0], 4, b_out_hp, lane, r8);
            #pragma unroll
            for (int k = 0; k < 8; ++k) {
                int j = lane + 32 * k;
                __stcg(&g_ahp[j], r8[k]);
                out[DEPTH * V_A + (t - 1) * V_HP + j] = r8[k];
            }
        }

        // gates_a = W_ih_a @ a + W_hh_a @ h_a + b    (8192 rows)
        for (int r = gw; r < 4 * H_A; r += NWARPS) {
            float p = wdotp(W_ih_a + (size_t)r * V_A, sa,  V_A / 4, lane)
                    + wdotp(W_hh_a + (size_t)r * H_A, sha, H_A / 4, lane);
            p = wred(p);
            if (lane == 0) __stcg(&g_gates_a[r], p + b_ih_a[r] + b_hh_a[r]);
        }
        // h_sum = relu(W_sum @ h_hp + b)             (2048 rows)
        for (int r = gw; r < H_A; r += NWARPS) {
            float p = wred(wdotp(W_sum + (size_t)r * H_HP, shhp, H_HP / 4, lane));
            if (lane == 0) __stcg(&g_hsum[r], fmaxf(p + b_sum[r], 0.f));
        }
        // gates_hp = W_hh_hp @ c_hp + b_ih + b_hh    (16384 rows, 268 MB)
        for (int r = gw; r < 4 * H_HP; r += NWARPS) {
            float p = wred(wdotp(W_hh_hp + (size_t)r * H_HP, schp, H_HP / 4, lane));
            if (lane == 0) __stcg(&g_gates_hp[r], p + b_ih_hp[r] + b_hh_hp[r]);
        }
        grid_sync();

        // ================= S1: arch cell + logits_a partials =================
        if (blockIdx.x < 16) {
            float* sh2 = sm;                 // h_a(t), 2048
            const int cb = t & 1;
            for (int j = tid; j < H_A; j += NTHR) {
                float ig = __ldcg(&g_gates_a[j]);
                float fg = __ldcg(&g_gates_a[H_A + j]);
                float gg = __ldcg(&g_gates_a[2 * H_A + j]);
                float og = __ldcg(&g_gates_a[3 * H_A + j]);
                float cn = sigm(fg) * __ldcg(&g_ca[cb][j]) + sigm(ig) * tanhf(gg);
                float hn = sigm(og) * tanhf(cn);
                sh2[j] = hn;
                if (blockIdx.x == 0) { __stcg(&g_ha[j], hn); __stcg(&g_ca[1 - cb][j], cn); }
            }
            __syncthreads();
            // logits_a partials: 512 warps (blocks 0-15), row = gw&255, K-chunk = gw>>8
            if (gw < 512) {
                int r  = gw & (V_A - 1);
                int ch = gw >> 8;
                float p = wred(wdotp(W_out_a + (size_t)r * H_A + ch * 1024, sh2 + ch * 1024, 256, lane));
                if (lane == 0) __stcg(&g_lpa[ch][r], p);
            }
        }
        grid_sync();

        // ================= S2: softmax(a) + W_ih_hp accumulate =================
        {
            float* sinp = sm;  // [a(t) | a_hp(t-1)] = 512
            if (wid == 0) {
                float r8[8];
                warp_softmax_256(&g_lpa[0][0], 2, b_out_a, lane, r8);
                #pragma unroll
                for (int k = 0; k < 8; ++k) {
                    int j = lane + 32 * k;
                    sinp[j] = r8[k];
                    if (blockIdx.x == 0) { __stcg(&g_a[j], r8[k]); out[t * V_A + j] = r8[k]; }
                }
            } else if (wid == 1) {
                for (int j = lane; j < V_HP; j += 32) sinp[V_A + j] = __ldcg(&g_ahp[j]);
            }
            __syncthreads();
            for (int r = gw; r < 4 * H_HP; r += NWARPS) {
                float p = wred(wdotp(W_ih_hp + (size_t)r * (V_A + V_HP), sinp, (V_A + V_HP) / 4, lane));
                if (lane == 0) __stcg(&g_gates_hp[r], __ldcg(&g_gates_hp[r]) + p);
            }
        }
        grid_sync();

        // ================= S3: hp cell + logits_hp partials =================
        // NOTE swapped hx in the reference: the LSTM h-input was c_hp(t-1) (already
        // consumed by the GEMV), the CELL state is prev_h_hp = concat(h_a(t), h_sum).
        if (blockIdx.x < 32) {
            float* sh2 = sm;                 // h_hp(t), 4096
            for (int j = tid; j < H_HP; j += NTHR) {
                float ig = __ldcg(&g_gates_hp[j]);
                float fg = __ldcg(&g_gates_hp[H_HP + j]);
                float gg = __ldcg(&g_gates_hp[2 * H_HP + j]);
                float og = __ldcg(&g_gates_hp[3 * H_HP + j]);
                float pc = (j < H_A) ? __ldcg(&g_ha[j]) : __ldcg(&g_hsum[j - H_A]);
                float cn = sigm(fg) * pc + sigm(ig) * tanhf(gg);
                float hn = sigm(og) * tanhf(cn);
                sh2[j] = hn;
                if (blockIdx.x == 0) { __stcg(&g_hhp[j], hn); __stcg(&g_chp[j], cn); }
            }
            __syncthreads();
            // logits_hp partials: 1024 warps (blocks 0-31), row = gw&255, K-chunk = gw>>8
            if (gw < 1024) {
                int r  = gw & (V_HP - 1);
                int ch = gw >> 8;
                float p = wred(wdotp(W_out_hp + (size_t)r * H_HP + ch * 1024, sh2 + ch * 1024, 256, lane));
                if (lane == 0) __stcg(&g_lphp[ch][r], p);
            }
        }
        grid_sync();
    }

    // ================= epilogue: final a_hp row =================
    if (blockIdx.x == 0 && wid == 0) {
        float r8[8];
        warp_softmax_256(&g_lphp[0][0], 4, b_out_hp, lane, r8);
        #pragma unroll
        for (int k = 0; k < 8; ++k) {
            int j = lane + 32 * k;
            out[DEPTH * V_A + (DEPTH - 1) * V_HP + j] = r8[k];
        }
    }
}

extern "C" void kernel_launch(void* const* d_in, const int* in_sizes, int n_in,
                              void* d_out, int out_size) {
    (void)in_sizes; (void)n_in; (void)out_size;
    archdec_kernel<<<NBLK, NTHR>>>(
        (const float*)d_in[0],  (const float*)d_in[1],
        (const float*)d_in[2],  (const float*)d_in[3],
        (const float*)d_in[4],  (const float*)d_in[5],
        (const float*)d_in[6],  (const float*)d_in[7],
        (const float*)d_in[8],  (const float*)d_in[9],
        (const float*)d_in[10], (const float*)d_in[11],
        (const float*)d_in[12], (const float*)d_in[13],
        (const float*)d_in[14], (const float*)d_in[15],
        (float*)d_out);
}

// round 4
// speedup vs baseline: 1.5098x; 1.1774x over previous
#include <cuda_runtime.h>
#include <cuda_fp16.h>
#include <math.h>

#define V_A   256
#define V_HP  256
#define H_A   2048
#define H_HP  4096
#define DEPTH 12

#define NBLK 148
#define NTHR 1024
#define NWARP_BLK (NTHR / 32)
#define NWARPS (NBLK * NWARP_BLK)   // 4736

// ---------------- fp16 weight scratch (converted each launch, inside the graph) ----
#define SZ_IH_A   (4 * H_A * V_A)                    // 2,097,152
#define SZ_HH_A   (4 * H_A * H_A)                    // 16,777,216
#define SZ_SUM    ((H_HP / 2) * H_HP)                // 8,388,608
#define SZ_IH_HP  (4 * H_HP * (V_A + V_HP))          // 8,388,608
#define SZ_HH_HP  (4 * H_HP * H_HP)                  // 67,108,864
#define SZ_OUT_A  (V_A * H_A)                        // 524,288
#define SZ_OUT_HP (V_HP * H_HP)                      // 1,048,576

#define OFF_IH_A   0
#define OFF_HH_A   (OFF_IH_A + SZ_IH_A)
#define OFF_SUM    (OFF_HH_A + SZ_HH_A)
#define OFF_IH_HP  (OFF_SUM + SZ_SUM)
#define OFF_HH_HP  (OFF_IH_HP + SZ_IH_HP)
#define OFF_OUT_A  (OFF_HH_HP + SZ_HH_HP)
#define OFF_OUT_HP (OFF_OUT_A + SZ_OUT_A)
#define SZ_TOTAL   (OFF_OUT_HP + SZ_OUT_HP)          // 104,333,312 halfs = 208.7 MB

__device__ __align__(16) __half g_w[SZ_TOTAL];

// ---------------- persistent device state ----------------
__device__ float g_a[V_A];
__device__ float g_ahp[V_HP];
__device__ float g_ha[H_A];
__device__ float g_ca[2][H_A];
__device__ float g_hhp[H_HP];
__device__ float g_chp[H_HP];
__device__ float g_gates_a[4 * H_A];
__device__ float g_gates_hp[4 * H_HP];
__device__ float g_hsum[H_A];
__device__ float g_lpa[2][V_A];
__device__ float g_lphp[4][V_HP];
__device__ unsigned int g_bar_count = 0;
__device__ unsigned int g_bar_gen = 0;

// ---------------- conversion kernel: fp32 -> fp16 ----------------
__device__ __forceinline__ void conv_arr(const float* __restrict__ s, __half* __restrict__ d,
                                         size_t n, size_t gtid, size_t gstride) {
    const float4* __restrict__ s4 = (const float4*)s;
    __half2* __restrict__ d2 = (__half2*)d;
    size_t n4 = n >> 2;
    for (size_t i = gtid; i < n4; i += gstride) {
        float4 v = s4[i];
        d2[2 * i]     = __floats2half2_rn(v.x, v.y);
        d2[2 * i + 1] = __floats2half2_rn(v.z, v.w);
    }
}

__global__ void __launch_bounds__(NTHR, 1) convert_kernel(
    const float* __restrict__ W_ih_a, const float* __restrict__ W_hh_a,
    const float* __restrict__ W_sum,  const float* __restrict__ W_ih_hp,
    const float* __restrict__ W_hh_hp, const float* __restrict__ W_out_a,
    const float* __restrict__ W_out_hp)
{
    size_t gtid = (size_t)blockIdx.x * NTHR + threadIdx.x;
    size_t gstride = (size_t)gridDim.x * NTHR;
    conv_arr(W_ih_a,  g_w + OFF_IH_A,   SZ_IH_A,   gtid, gstride);
    conv_arr(W_hh_a,  g_w + OFF_HH_A,   SZ_HH_A,   gtid, gstride);
    conv_arr(W_sum,   g_w + OFF_SUM,    SZ_SUM,    gtid, gstride);
    conv_arr(W_ih_hp, g_w + OFF_IH_HP,  SZ_IH_HP,  gtid, gstride);
    conv_arr(W_hh_hp, g_w + OFF_HH_HP,  SZ_HH_HP,  gtid, gstride);
    conv_arr(W_out_a, g_w + OFF_OUT_A,  SZ_OUT_A,  gtid, gstride);
    conv_arr(W_out_hp,g_w + OFF_OUT_HP, SZ_OUT_HP, gtid, gstride);
}

// ---------------- grid barrier (all 148 blocks resident) ----------------
__device__ __forceinline__ void grid_sync() {
    __syncthreads();
    if (threadIdx.x == 0) {
        __threadfence();
        volatile unsigned int* vgen = &g_bar_gen;
        unsigned int gen = *vgen;
        unsigned int ticket = atomicAdd(&g_bar_count, 1);
        if (ticket == gridDim.x - 1) {
            g_bar_count = 0;
            __threadfence();
            *vgen = gen + 1;
        } else {
            while (*vgen == gen) { }
        }
    }
    __syncthreads();
}

__device__ __forceinline__ float sigm(float x) { return 1.0f / (1.0f + expf(-x)); }

__device__ __forceinline__ float wred(float v) {
    #pragma unroll
    for (int o = 16; o; o >>= 1) v += __shfl_xor_sync(0xffffffffu, v, o);
    return v;
}

// 8 fp16 weights (uint4) dotted with 8 fp32 x values (two float4), fp32 accumulate.
__device__ __forceinline__ float dot8h(const uint4& w, const float4& xA, const float4& xB) {
    float2 c0 = __half22float2(*reinterpret_cast<const __half2*>(&w.x));
    float2 c1 = __half22float2(*reinterpret_cast<const __half2*>(&w.y));
    float2 c2 = __half22float2(*reinterpret_cast<const __half2*>(&w.z));
    float2 c3 = __half22float2(*reinterpret_cast<const __half2*>(&w.w));
    float a = fmaf(c0.x, xA.x, fmaf(c0.y, xA.y, fmaf(c1.x, xA.z, fmaf(c1.y, xA.w, 0.f))));
    return fmaf(c2.x, xB.x, fmaf(c2.y, xB.y, fmaf(c3.x, xB.z, fmaf(c3.y, xB.w, a))));
}

// lane-partial dot of an fp16 W row with fp32 x (shared). K8 = K/8, multiple of 64.
__device__ __forceinline__ float wdotp_h(const __half* __restrict__ W,
                                         const float* __restrict__ xs,
                                         int K8, int lane) {
    const uint4* __restrict__ W8 = (const uint4*)W;
    const float4* __restrict__ x4 = (const float4*)xs;
    float a0 = 0.f, a1 = 0.f;
    #pragma unroll 2
    for (int i = lane; i < K8; i += 64) {
        uint4 w  = W8[i];
        uint4 w2 = W8[i + 32];
        a0 += dot8h(w,  x4[2 * i],        x4[2 * i + 1]);
        a1 += dot8h(w2, x4[2 * (i + 32)], x4[2 * (i + 32) + 1]);
    }
    return a0 + a1;
}

// K=256 special case: each lane loads exactly one uint4 (8 halfs).
__device__ __forceinline__ float dot256_h(const __half* __restrict__ W,
                                          const float* __restrict__ xs, int lane) {
    const uint4* __restrict__ W8 = (const uint4*)W;
    const float4* __restrict__ x4 = (const float4*)xs;
    uint4 w = W8[lane];
    return dot8h(w, x4[2 * lane], x4[2 * lane + 1]);
}

// warp-collective softmax over 256 logits from nch K-split partials + bias.
__device__ __forceinline__ void warp_softmax_256(const float* parts, int nch,
                                                 const float* __restrict__ bias,
                                                 int lane, float* res8) {
    float v[8];
    float mx = -1e30f;
    #pragma unroll
    for (int k = 0; k < 8; ++k) {
        int j = lane + 32 * k;
        float s = bias[j];
        for (int c = 0; c < nch; ++c) s += __ldcg(&parts[c * 256 + j]);
        v[k] = s;
        mx = fmaxf(mx, s);
    }
    #pragma unroll
    for (int o = 16; o; o >>= 1) mx = fmaxf(mx, __shfl_xor_sync(0xffffffffu, mx, o));
    float sum = 0.f;
    #pragma unroll
    for (int k = 0; k < 8; ++k) { v[k] = expf(v[k] - mx); sum += v[k]; }
    sum = wred(sum);
    #pragma unroll
    for (int k = 0; k < 8; ++k) res8[k] = v[k] / sum;
}

__global__ void __launch_bounds__(NTHR, 1) archdec_kernel(
    const float* __restrict__ xa,     const float* __restrict__ xhp,
    const float* __restrict__ b_ih_a, const float* __restrict__ b_hh_a,
    const float* __restrict__ b_out_a, const float* __restrict__ b_sum,
    const float* __restrict__ b_ih_hp, const float* __restrict__ b_hh_hp,
    const float* __restrict__ b_out_hp,
    float* __restrict__ out)
{
    __shared__ float sm[V_A + H_A + H_HP + H_HP];   // 10496 floats = 41 KB
    const int tid  = threadIdx.x;
    const int lane = tid & 31;
    const int wid  = tid >> 5;
    const int gw   = blockIdx.x * NWARP_BLK + wid;

    const __half* __restrict__ Wih_a  = g_w + OFF_IH_A;
    const __half* __restrict__ Whh_a  = g_w + OFF_HH_A;
    const __half* __restrict__ Wsum   = g_w + OFF_SUM;
    const __half* __restrict__ Wih_hp = g_w + OFF_IH_HP;
    const __half* __restrict__ Whh_hp = g_w + OFF_HH_HP;
    const __half* __restrict__ Wout_a = g_w + OFF_OUT_A;
    const __half* __restrict__ Wout_hp= g_w + OFF_OUT_HP;

    // -------- init state (every launch) --------
    {
        int j = blockIdx.x * NTHR + tid;
        if (j < H_HP) {
            if (j < V_A) { __stcg(&g_a[j], 1.0f / V_A); __stcg(&g_ahp[j], 1.0f / V_HP); }
            if (j < H_A) { __stcg(&g_ha[j], xa[j]); __stcg(&g_ca[0][j], 0.f); }
            __stcg(&g_hhp[j], xhp[j]);
            __stcg(&g_chp[j], 0.f);
        }
    }
    grid_sync();

    for (int t = 0; t < DEPTH; ++t) {
        // ================= PHASE 1: big GEMVs on prev-step state =================
        float* sa   = sm;                 // 256
        float* sha  = sm + V_A;           // 2048
        float* shhp = sha + H_A;          // 4096
        float* schp = shhp + H_HP;        // 4096
        for (int j = tid; j < V_A;  j += NTHR) sa[j]  = __ldcg(&g_a[j]);
        for (int j = tid; j < H_A;  j += NTHR) sha[j] = __ldcg(&g_ha[j]);
        for (int j = tid; j < H_HP; j += NTHR) { shhp[j] = __ldcg(&g_hhp[j]); schp[j] = __ldcg(&g_chp[j]); }
        __syncthreads();

        // block 0 / warp 0: finish previous step's a_hp = softmax(logits_hp(t-1))
        if (t > 0 && blockIdx.x == 0 && wid == 0) {
            float r8[8];
            warp_softmax_256(&g_lphp[0][0], 4, b_out_hp, lane, r8);
            #pragma unroll
            for (int k = 0; k < 8; ++k) {
                int j = lane + 32 * k;
                __stcg(&g_ahp[j], r8[k]);
                out[DEPTH * V_A + (t - 1) * V_HP + j] = r8[k];
            }
        }

        // gates_a = W_ih_a @ a + W_hh_a @ h_a + b    (8192 rows)
        for (int r = gw; r < 4 * H_A; r += NWARPS) {
            float p = dot256_h(Wih_a + (size_t)r * V_A, sa, lane)
                    + wdotp_h(Whh_a + (size_t)r * H_A, sha, H_A / 8, lane);
            p = wred(p);
            if (lane == 0) __stcg(&g_gates_a[r], p + b_ih_a[r] + b_hh_a[r]);
        }
        // h_sum = relu(W_sum @ h_hp + b)             (2048 rows)
        for (int r = gw; r < H_A; r += NWARPS) {
            float p = wred(wdotp_h(Wsum + (size_t)r * H_HP, shhp, H_HP / 8, lane));
            if (lane == 0) __stcg(&g_hsum[r], fmaxf(p + b_sum[r], 0.f));
        }
        // gates_hp = W_hh_hp @ c_hp + b_ih + b_hh    (16384 rows, 134 MB fp16)
        for (int r = gw; r < 4 * H_HP; r += NWARPS) {
            float p = wred(wdotp_h(Whh_hp + (size_t)r * H_HP, schp, H_HP / 8, lane));
            if (lane == 0) __stcg(&g_gates_hp[r], p + b_ih_hp[r] + b_hh_hp[r]);
        }
        grid_sync();

        // ================= S1: arch cell + logits_a partials =================
        if (blockIdx.x < 16) {
            float* sh2 = sm;                 // h_a(t), 2048
            const int cb = t & 1;
            for (int j = tid; j < H_A; j += NTHR) {
                float ig = __ldcg(&g_gates_a[j]);
                float fg = __ldcg(&g_gates_a[H_A + j]);
                float gg = __ldcg(&g_gates_a[2 * H_A + j]);
                float og = __ldcg(&g_gates_a[3 * H_A + j]);
                float cn = sigm(fg) * __ldcg(&g_ca[cb][j]) + sigm(ig) * tanhf(gg);
                float hn = sigm(og) * tanhf(cn);
                sh2[j] = hn;
                if (blockIdx.x == 0) { __stcg(&g_ha[j], hn); __stcg(&g_ca[1 - cb][j], cn); }
            }
            __syncthreads();
            // logits_a partials: 512 warps (blocks 0-15), row = gw&255, K-chunk = gw>>8
            if (gw < 512) {
                int r  = gw & (V_A - 1);
                int ch = gw >> 8;
                float p = wred(wdotp_h(Wout_a + (size_t)r * H_A + ch * 1024, sh2 + ch * 1024, 128, lane));
                if (lane == 0) __stcg(&g_lpa[ch][r], p);
            }
        }
        grid_sync();

        // ================= S2: softmax(a) + W_ih_hp accumulate =================
        {
            float* sinp = sm;  // [a(t) | a_hp(t-1)] = 512
            if (wid == 0) {
                float r8[8];
                warp_softmax_256(&g_lpa[0][0], 2, b_out_a, lane, r8);
                #pragma unroll
                for (int k = 0; k < 8; ++k) {
                    int j = lane + 32 * k;
                    sinp[j] = r8[k];
                    if (blockIdx.x == 0) { __stcg(&g_a[j], r8[k]); out[t * V_A + j] = r8[k]; }
                }
            } else if (wid == 1) {
                for (int j = lane; j < V_HP; j += 32) sinp[V_A + j] = __ldcg(&g_ahp[j]);
            }
            __syncthreads();
            for (int r = gw; r < 4 * H_HP; r += NWARPS) {
                float p = wred(wdotp_h(Wih_hp + (size_t)r * (V_A + V_HP), sinp, (V_A + V_HP) / 8, lane));
                if (lane == 0) __stcg(&g_gates_hp[r], __ldcg(&g_gates_hp[r]) + p);
            }
        }
        grid_sync();

        // ================= S3: hp cell + logits_hp partials =================
        // NOTE swapped hx in the reference: the LSTM h-input was c_hp(t-1) (already
        // consumed by the GEMV), the CELL state is prev_h_hp = concat(h_a(t), h_sum).
        if (blockIdx.x < 32) {
            float* sh2 = sm;                 // h_hp(t), 4096
            for (int j = tid; j < H_HP; j += NTHR) {
                float ig = __ldcg(&g_gates_hp[j]);
                float fg = __ldcg(&g_gates_hp[H_HP + j]);
                float gg = __ldcg(&g_gates_hp[2 * H_HP + j]);
                float og = __ldcg(&g_gates_hp[3 * H_HP + j]);
                float pc = (j < H_A) ? __ldcg(&g_ha[j]) : __ldcg(&g_hsum[j - H_A]);
                float cn = sigm(fg) * pc + sigm(ig) * tanhf(gg);
                float hn = sigm(og) * tanhf(cn);
                sh2[j] = hn;
                if (blockIdx.x == 0) { __stcg(&g_hhp[j], hn); __stcg(&g_chp[j], cn); }
            }
            __syncthreads();
            // logits_hp partials: 1024 warps (blocks 0-31), row = gw&255, K-chunk = gw>>8
            if (gw < 1024) {
                int r  = gw & (V_HP - 1);
                int ch = gw >> 8;
                float p = wred(wdotp_h(Wout_hp + (size_t)r * H_HP + ch * 1024, sh2 + ch * 1024, 128, lane));
                if (lane == 0) __stcg(&g_lphp[ch][r], p);
            }
        }
        grid_sync();
    }

    // ================= epilogue: final a_hp row =================
    if (blockIdx.x == 0 && wid == 0) {
        float r8[8];
        warp_softmax_256(&g_lphp[0][0], 4, b_out_hp, lane, r8);
        #pragma unroll
        for (int k = 0; k < 8; ++k) {
            int j = lane + 32 * k;
            out[DEPTH * V_A + (DEPTH - 1) * V_HP + j] = r8[k];
        }
    }
}

extern "C" void kernel_launch(void* const* d_in, const int* in_sizes, int n_in,
                              void* d_out, int out_size) {
    (void)in_sizes; (void)n_in; (void)out_size;
    convert_kernel<<<NBLK, NTHR>>>(
        (const float*)d_in[2],   // W_ih_a
        (const float*)d_in[3],   // W_hh_a
        (const float*)d_in[8],   // W_sum
        (const float*)d_in[10],  // W_ih_hp
        (const float*)d_in[11],  // W_hh_hp
        (const float*)d_in[6],   // W_out_a
        (const float*)d_in[14]); // W_out_hp
    archdec_kernel<<<NBLK, NTHR>>>(
        (const float*)d_in[0],  (const float*)d_in[1],
        (const float*)d_in[4],  (const float*)d_in[5],
        (const float*)d_in[7],  (const float*)d_in[9],
        (const float*)d_in[12], (const float*)d_in[13],
        (const float*)d_in[15],
        (float*)d_out);
}

// round 5
// speedup vs baseline: 1.9287x; 1.2774x over previous
#include <cuda_runtime.h>
#include <cuda_fp16.h>
#include <math.h>

#define V_A   256
#define V_HP  256
#define H_A   2048
#define H_HP  4096
#define DEPTH 12

#define NBLK 148
#define NTHR 1024
#define NWARP_BLK (NTHR / 32)
#define NWARPS (NBLK * NWARP_BLK)   // 4736

// ---------------- fp16 weight scratch (converted each launch, inside the graph) ----
#define SZ_IH_A   (4 * H_A * V_A)
#define SZ_HH_A   (4 * H_A * H_A)
#define SZ_SUM    ((H_HP / 2) * H_HP)
#define SZ_IH_HP  (4 * H_HP * (V_A + V_HP))
#define SZ_HH_HP  (4 * H_HP * H_HP)
#define SZ_OUT_A  (V_A * H_A)
#define SZ_OUT_HP (V_HP * H_HP)

#define OFF_IH_A   0
#define OFF_HH_A   (OFF_IH_A + SZ_IH_A)
#define OFF_SUM    (OFF_HH_A + SZ_HH_A)
#define OFF_IH_HP  (OFF_SUM + SZ_SUM)
#define OFF_HH_HP  (OFF_IH_HP + SZ_IH_HP)
#define OFF_OUT_A  (OFF_HH_HP + SZ_HH_HP)
#define OFF_OUT_HP (OFF_OUT_A + SZ_OUT_A)
#define SZ_TOTAL   (OFF_OUT_HP + SZ_OUT_HP)          // 208.7 MB

__device__ __align__(16) __half g_w[SZ_TOTAL];

// ---------------- persistent device state ----------------
__device__ float g_a[V_A];
__device__ float g_ahp[V_HP];
__device__ float g_ha[H_A];
__device__ float g_ca[2][H_A];
__device__ float g_hhp[H_HP];
__device__ float g_chp[H_HP];
__device__ float g_gates_a[4 * H_A];
__device__ float g_gates_hp[4 * H_HP];
__device__ float g_hsum[H_A];
__device__ float g_lpa[2][V_A];
__device__ float g_lphp[4][V_HP];
__device__ unsigned int g_bar_count = 0;
__device__ unsigned int g_bar_gen = 0;

// ---------------- conversion kernel: fp32 -> fp16 ----------------
template<bool STREAM_DST>
__device__ __forceinline__ void conv_arr(const float* __restrict__ s, __half* __restrict__ d,
                                         size_t n, size_t gtid, size_t gstride) {
    const float4* __restrict__ s4 = (const float4*)s;
    __half2* __restrict__ d2 = (__half2*)d;
    size_t n4 = n >> 2;
    for (size_t i = gtid; i < n4; i += gstride) {
        float4 v = __ldcs(s4 + i);               // don't pollute L2 with fp32 source
        __half2 lo = __floats2half2_rn(v.x, v.y);
        __half2 hi = __floats2half2_rn(v.z, v.w);
        if (STREAM_DST) { __stcs(&d2[2 * i], lo); __stcs(&d2[2 * i + 1], hi); }
        else            { d2[2 * i] = lo;         d2[2 * i + 1] = hi; }
    }
}

__global__ void __launch_bounds__(NTHR, 1) convert_kernel(
    const float* __restrict__ W_ih_a, const float* __restrict__ W_hh_a,
    const float* __restrict__ W_sum,  const float* __restrict__ W_ih_hp,
    const float* __restrict__ W_hh_hp, const float* __restrict__ W_out_a,
    const float* __restrict__ W_out_hp)
{
    size_t gtid = (size_t)blockIdx.x * NTHR + threadIdx.x;
    size_t gstride = (size_t)gridDim.x * NTHR;
    // hh_hp first (streamed, evict-first), then the L2-resident set last
    conv_arr<true >(W_hh_hp, g_w + OFF_HH_HP, SZ_HH_HP, gtid, gstride);
    conv_arr<false>(W_ih_a,  g_w + OFF_IH_A,  SZ_IH_A,  gtid, gstride);
    conv_arr<false>(W_hh_a,  g_w + OFF_HH_A,  SZ_HH_A,  gtid, gstride);
    conv_arr<false>(W_sum,   g_w + OFF_SUM,   SZ_SUM,   gtid, gstride);
    conv_arr<false>(W_ih_hp, g_w + OFF_IH_HP, SZ_IH_HP, gtid, gstride);
    conv_arr<false>(W_out_a, g_w + OFF_OUT_A, SZ_OUT_A, gtid, gstride);
    conv_arr<false>(W_out_hp,g_w + OFF_OUT_HP,SZ_OUT_HP,gtid, gstride);
}

// ---------------- grid barrier (all 148 blocks resident) ----------------
__device__ __forceinline__ void grid_sync() {
    __syncthreads();
    if (threadIdx.x == 0) {
        __threadfence();
        volatile unsigned int* vgen = &g_bar_gen;
        unsigned int gen = *vgen;
        unsigned int ticket = atomicAdd(&g_bar_count, 1);
        if (ticket == gridDim.x - 1) {
            g_bar_count = 0;
            __threadfence();
            *vgen = gen + 1;
        } else {
            while (*vgen == gen) { }
        }
    }
    __syncthreads();
}

__device__ __forceinline__ float sigm(float x) { return 1.0f / (1.0f + expf(-x)); }

__device__ __forceinline__ float wred(float v) {
    #pragma unroll
    for (int o = 16; o; o >>= 1) v += __shfl_xor_sync(0xffffffffu, v, o);
    return v;
}

// 8 fp16 weights (uint4) dotted with 8 fp32 x values (two float4), fp32 accumulate.
__device__ __forceinline__ float dot8h(const uint4& w, const float4& xA, const float4& xB) {
    float2 c0 = __half22float2(*reinterpret_cast<const __half2*>(&w.x));
    float2 c1 = __half22float2(*reinterpret_cast<const __half2*>(&w.y));
    float2 c2 = __half22float2(*reinterpret_cast<const __half2*>(&w.z));
    float2 c3 = __half22float2(*reinterpret_cast<const __half2*>(&w.w));
    float a = fmaf(c0.x, xA.x, fmaf(c0.y, xA.y, fmaf(c1.x, xA.z, fmaf(c1.y, xA.w, 0.f))));
    return fmaf(c2.x, xB.x, fmaf(c2.y, xB.y, fmaf(c3.x, xB.z, fmaf(c3.y, xB.w, a))));
}

template<bool STREAM>
__device__ __forceinline__ uint4 ldw(const uint4* __restrict__ p) {
    return STREAM ? __ldcs(p) : __ldg(p);
}

// TWO adjacent rows per warp: doubled weight-load MLP, x loaded once for both rows.
// Returns UNREDUCED lane partials in o0/o1. K8 = K/8, multiple of 32.
template<bool STREAM>
__device__ __forceinline__ void wdotp2_h(const __half* __restrict__ W0,
                                         const __half* __restrict__ W1,
                                         const float* __restrict__ xs,
                                         int K8, int lane, float& o0, float& o1) {
    const uint4* __restrict__ A = (const uint4*)W0;
    const uint4* __restrict__ B = (const uint4*)W1;
    const float4* __restrict__ x4 = (const float4*)xs;
    float a = 0.f, b = 0.f;
    #pragma unroll 2
    for (int i = lane; i < K8; i += 32) {
        uint4 wa = ldw<STREAM>(A + i);
        uint4 wb = ldw<STREAM>(B + i);
        float4 xA = x4[2 * i], xB = x4[2 * i + 1];
        a += dot8h(wa, xA, xB);
        b += dot8h(wb, xA, xB);
    }
    o0 = a; o1 = b;
}

// single-row lane-partial dot (small logits GEMVs). K8 multiple of 32.
__device__ __forceinline__ float wdotp_h(const __half* __restrict__ W,
                                         const float* __restrict__ xs,
                                         int K8, int lane) {
    const uint4* __restrict__ A = (const uint4*)W;
    const float4* __restrict__ x4 = (const float4*)xs;
    float a = 0.f;
    #pragma unroll 4
    for (int i = lane; i < K8; i += 32) {
        uint4 w = __ldg(A + i);
        a += dot8h(w, x4[2 * i], x4[2 * i + 1]);
    }
    return a;
}

// warp-collective softmax over 256 logits from nch K-split partials + bias.
__device__ __forceinline__ void warp_softmax_256(const float* parts, int nch,
                                                 const float* __restrict__ bias,
                                                 int lane, float* res8) {
    float v[8];
    float mx = -1e30f;
    #pragma unroll
    for (int k = 0; k < 8; ++k) {
        int j = lane + 32 * k;
        float s = bias[j];
        for (int c = 0; c < nch; ++c) s += __ldcg(&parts[c * 256 + j]);
        v[k] = s;
        mx = fmaxf(mx, s);
    }
    #pragma unroll
    for (int o = 16; o; o >>= 1) mx = fmaxf(mx, __shfl_xor_sync(0xffffffffu, mx, o));
    float sum = 0.f;
    #pragma unroll
    for (int k = 0; k < 8; ++k) { v[k] = expf(v[k] - mx); sum += v[k]; }
    sum = wred(sum);
    #pragma unroll
    for (int k = 0; k < 8; ++k) res8[k] = v[k] / sum;
}

// Phase-1 unified pair-task space
#define NP_HP  (4 * H_HP / 2)          // 8192
#define NP_GA  (4 * H_A / 2)           // 4096
#define NP_SUM (H_A / 2)               // 1024
#define NP_ALL (NP_HP + NP_GA + NP_SUM) // 13312

__global__ void __launch_bounds__(NTHR, 1) archdec_kernel(
    const float* __restrict__ xa,     const float* __restrict__ xhp,
    const float* __restrict__ b_ih_a, const float* __restrict__ b_hh_a,
    const float* __restrict__ b_out_a, const float* __restrict__ b_sum,
    const float* __restrict__ b_ih_hp, const float* __restrict__ b_hh_hp,
    const float* __restrict__ b_out_hp,
    float* __restrict__ out)
{
    __shared__ float sm[V_A + H_A + H_HP + H_HP];   // 41 KB
    const int tid  = threadIdx.x;
    const int lane = tid & 31;
    const int wid  = tid >> 5;
    const int gw   = blockIdx.x * NWARP_BLK + wid;

    const __half* __restrict__ Wih_a  = g_w + OFF_IH_A;
    const __half* __restrict__ Whh_a  = g_w + OFF_HH_A;
    const __half* __restrict__ Wsum   = g_w + OFF_SUM;
    const __half* __restrict__ Wih_hp = g_w + OFF_IH_HP;
    const __half* __restrict__ Whh_hp = g_w + OFF_HH_HP;
    const __half* __restrict__ Wout_a = g_w + OFF_OUT_A;
    const __half* __restrict__ Wout_hp= g_w + OFF_OUT_HP;

    // -------- init state (every launch) --------
    {
        int j = blockIdx.x * NTHR + tid;
        if (j < H_HP) {
            if (j < V_A) { __stcg(&g_a[j], 1.0f / V_A); __stcg(&g_ahp[j], 1.0f / V_HP); }
            if (j < H_A) { __stcg(&g_ha[j], xa[j]); __stcg(&g_ca[0][j], 0.f); }
            __stcg(&g_hhp[j], xhp[j]);
            __stcg(&g_chp[j], 0.f);
        }
    }
    grid_sync();

    for (int t = 0; t < DEPTH; ++t) {
        // ================= PHASE 1: big GEMVs on prev-step state =================
        float* sa   = sm;                 // 256
        float* sha  = sm + V_A;           // 2048
        float* shhp = sha + H_A;          // 4096
        float* schp = shhp + H_HP;        // 4096
        for (int j = tid; j < V_A;  j += NTHR) sa[j]  = __ldcg(&g_a[j]);
        for (int j = tid; j < H_A;  j += NTHR) sha[j] = __ldcg(&g_ha[j]);
        for (int j = tid; j < H_HP; j += NTHR) { shhp[j] = __ldcg(&g_hhp[j]); schp[j] = __ldcg(&g_chp[j]); }
        __syncthreads();

        // block 0 / warp 0: finish previous step's a_hp = softmax(logits_hp(t-1))
        if (t > 0 && blockIdx.x == 0 && wid == 0) {
            float r8[8];
            warp_softmax_256(&g_lphp[0][0], 4, b_out_hp, lane, r8);
            #pragma unroll
            for (int k = 0; k < 8; ++k) {
                int j = lane + 32 * k;
                __stcg(&g_ahp[j], r8[k]);
                out[DEPTH * V_A + (t - 1) * V_HP + j] = r8[k];
            }
        }

        // unified pair-task loop (load-balanced across all 4736 warps)
        for (int p = gw; p < NP_ALL; p += NWARPS) {
            if (p < NP_HP) {
                // gates_hp = W_hh_hp @ c_hp + biases (STREAMING: evict-first)
                int r = 2 * p;
                float o0, o1;
                wdotp2_h<true>(Whh_hp + (size_t)r * H_HP, Whh_hp + (size_t)(r + 1) * H_HP,
                               schp, H_HP / 8, lane, o0, o1);
                o0 = wred(o0); o1 = wred(o1);
                if (lane < 2) {
                    int rr = r + lane;
                    float v = lane ? o1 : o0;
                    __stcg(&g_gates_hp[rr], v + b_ih_hp[rr] + b_hh_hp[rr]);
                }
            } else if (p < NP_HP + NP_GA) {
                // gates_a = W_ih_a @ a + W_hh_a @ h_a + biases (L2-resident)
                int r = 2 * (p - NP_HP);
                const uint4* __restrict__ I0 = (const uint4*)(Wih_a + (size_t)r * V_A);
                const uint4* __restrict__ I1 = (const uint4*)(Wih_a + (size_t)(r + 1) * V_A);
                const float4* __restrict__ sa4 = (const float4*)sa;
                float4 xA = sa4[2 * lane], xB = sa4[2 * lane + 1];
                float o0 = dot8h(__ldg(I0 + lane), xA, xB);
                float o1 = dot8h(__ldg(I1 + lane), xA, xB);
                float h0, h1;
                wdotp2_h<false>(Whh_a + (size_t)r * H_A, Whh_a + (size_t)(r + 1) * H_A,
                                sha, H_A / 8, lane, h0, h1);
                o0 = wred(o0 + h0); o1 = wred(o1 + h1);
                if (lane < 2) {
                    int rr = r + lane;
                    float v = lane ? o1 : o0;
                    __stcg(&g_gates_a[rr], v + b_ih_a[rr] + b_hh_a[rr]);
                }
            } else {
                // h_sum = relu(W_sum @ h_hp + b) (L2-resident)
                int r = 2 * (p - NP_HP - NP_GA);
                float o0, o1;
                wdotp2_h<false>(Wsum + (size_t)r * H_HP, Wsum + (size_t)(r + 1) * H_HP,
                                shhp, H_HP / 8, lane, o0, o1);
                o0 = wred(o0); o1 = wred(o1);
                if (lane < 2) {
                    int rr = r + lane;
                    float v = lane ? o1 : o0;
                    __stcg(&g_hsum[rr], fmaxf(v + b_sum[rr], 0.f));
                }
            }
        }
        grid_sync();

        // ================= S1: arch cell + logits_a partials =================
        if (blockIdx.x < 16) {
            float* sh2 = sm;                 // h_a(t), 2048
            const int cb = t & 1;
            for (int j = tid; j < H_A; j += NTHR) {
                float ig = __ldcg(&g_gates_a[j]);
                float fg = __ldcg(&g_gates_a[H_A + j]);
                float gg = __ldcg(&g_gates_a[2 * H_A + j]);
                float og = __ldcg(&g_gates_a[3 * H_A + j]);
                float cn = sigm(fg) * __ldcg(&g_ca[cb][j]) + sigm(ig) * tanhf(gg);
                float hn = sigm(og) * tanhf(cn);
                sh2[j] = hn;
                if (blockIdx.x == 0) { __stcg(&g_ha[j], hn); __stcg(&g_ca[1 - cb][j], cn); }
            }
            __syncthreads();
            if (gw < 512) {   // row = gw&255, K-chunk = gw>>8 (1024 elems)
                int r  = gw & (V_A - 1);
                int ch = gw >> 8;
                float p = wred(wdotp_h(Wout_a + (size_t)r * H_A + ch * 1024, sh2 + ch * 1024, 128, lane));
                if (lane == 0) __stcg(&g_lpa[ch][r], p);
            }
        }
        grid_sync();

        // ================= S2: softmax(a) + W_ih_hp accumulate =================
        {
            float* sinp = sm;  // [a(t) | a_hp(t-1)] = 512
            if (wid == 0) {
                float r8[8];
                warp_softmax_256(&g_lpa[0][0], 2, b_out_a, lane, r8);
                #pragma unroll
                for (int k = 0; k < 8; ++k) {
                    int j = lane + 32 * k;
                    sinp[j] = r8[k];
                    if (blockIdx.x == 0) { __stcg(&g_a[j], r8[k]); out[t * V_A + j] = r8[k]; }
                }
            } else if (wid == 1) {
                for (int j = lane; j < V_HP; j += 32) sinp[V_A + j] = __ldcg(&g_ahp[j]);
            }
            __syncthreads();
            for (int p = gw; p < 4 * H_HP / 2; p += NWARPS) {
                int r = 2 * p;
                float o0, o1;
                wdotp2_h<false>(Wih_hp + (size_t)r * (V_A + V_HP),
                                Wih_hp + (size_t)(r + 1) * (V_A + V_HP),
                                sinp, (V_A + V_HP) / 8, lane, o0, o1);
                o0 = wred(o0); o1 = wred(o1);
                if (lane < 2) {
                    int rr = r + lane;
                    float v = lane ? o1 : o0;
                    __stcg(&g_gates_hp[rr], __ldcg(&g_gates_hp[rr]) + v);
                }
            }
        }
        grid_sync();

        // ================= S3: hp cell + logits_hp partials =================
        // NOTE swapped hx in the reference: LSTM h-input was c_hp(t-1) (already consumed
        // by the GEMV); the CELL state is prev_h_hp = concat(h_a(t), h_sum).
        if (blockIdx.x < 32) {
            float* sh2 = sm;                 // h_hp(t), 4096
            for (int j = tid; j < H_HP; j += NTHR) {
                float ig = __ldcg(&g_gates_hp[j]);
                float fg = __ldcg(&g_gates_hp[H_HP + j]);
                float gg = __ldcg(&g_gates_hp[2 * H_HP + j]);
                float og = __ldcg(&g_gates_hp[3 * H_HP + j]);
                float pc = (j < H_A) ? __ldcg(&g_ha[j]) : __ldcg(&g_hsum[j - H_A]);
                float cn = sigm(fg) * pc + sigm(ig) * tanhf(gg);
                float hn = sigm(og) * tanhf(cn);
                sh2[j] = hn;
                if (blockIdx.x == 0) { __stcg(&g_hhp[j], hn); __stcg(&g_chp[j], cn); }
            }
            __syncthreads();
            if (gw < 1024) {   // row = gw&255, K-chunk = gw>>8 (1024 elems)
                int r  = gw & (V_HP - 1);
                int ch = gw >> 8;
                float p = wred(wdotp_h(Wout_hp + (size_t)r * H_HP + ch * 1024, sh2 + ch * 1024, 128, lane));
                if (lane == 0) __stcg(&g_lphp[ch][r], p);
            }
        }
        grid_sync();
    }

    // ================= epilogue: final a_hp row =================
    if (blockIdx.x == 0 && wid == 0) {
        float r8[8];
        warp_softmax_256(&g_lphp[0][0], 4, b_out_hp, lane, r8);
        #pragma unroll
        for (int k = 0; k < 8; ++k) {
            int j = lane + 32 * k;
            out[DEPTH * V_A + (DEPTH - 1) * V_HP + j] = r8[k];
        }
    }
}

extern "C" void kernel_launch(void* const* d_in, const int* in_sizes, int n_in,
                              void* d_out, int out_size) {
    (void)in_sizes; (void)n_in; (void)out_size;
    convert_kernel<<<NBLK, NTHR>>>(
        (const float*)d_in[2],   // W_ih_a
        (const float*)d_in[3],   // W_hh_a
        (const float*)d_in[8],   // W_sum
        (const float*)d_in[10],  // W_ih_hp
        (const float*)d_in[11],  // W_hh_hp
        (const float*)d_in[6],   // W_out_a
        (const float*)d_in[14]); // W_out_hp
    archdec_kernel<<<NBLK, NTHR>>>(
        (const float*)d_in[0],  (const float*)d_in[1],
        (const float*)d_in[4],  (const float*)d_in[5],
        (const float*)d_in[7],  (const float*)d_in[9],
        (const float*)d_in[12], (const float*)d_in[13],
        (const float*)d_in[15],
        (float*)d_out);
}